// round 14
// baseline (speedup 1.0000x reference)
#include <cuda_runtime.h>
#include <cuda_bf16.h>

typedef unsigned int u32;
typedef unsigned long long u64;

// B=2,H=16,S=2048,D=64. d_out = [output | attn].
// k0 pack_mask (int4); k1 rowsum (1-MMA bf16-hi, 512thr/128rows) -> g_rowinv;
// k2 main (512thr/128rows, inline LDG, 3-MMA exact S, normalized attn
//     written once, PV 3-MMA -> O).

#define STB 144
// main kernel smem (128 q-rows)
#define QH_OFF 0
#define QL_OFF 18432
#define KH_OFF 36864
#define KL_OFF 55296
#define VH_OFF 73728
#define VL_OFF 92160
#define SI_OFF 110592
#define SM_TOTAL 111104
// rowsum smem (128 q-rows)
#define RS_QH 0
#define RS_KH 18432
#define RS_RS 36864
#define RS_TOTAL 37888

__device__ u32 g_mask_bits[2 * 2048 * 64];
__device__ float g_rowinv[2 * 16 * 2048];

__device__ __forceinline__ u32 smem_u32(const void* p) {
    u32 a;
    asm("{ .reg .u64 t; cvta.to.shared.u64 t, %1; cvt.u32.u64 %0, t; }" : "=r"(a) : "l"(p));
    return a;
}
__device__ __forceinline__ void LDSM4(u32 a, u32& r0, u32& r1, u32& r2, u32& r3) {
    asm volatile("ldmatrix.sync.aligned.m8n8.x4.shared.b16 {%0,%1,%2,%3}, [%4];"
                 : "=r"(r0), "=r"(r1), "=r"(r2), "=r"(r3) : "r"(a));
}
__device__ __forceinline__ void LDSM4T(u32 a, u32& r0, u32& r1, u32& r2, u32& r3) {
    asm volatile("ldmatrix.sync.aligned.m8n8.x4.trans.shared.b16 {%0,%1,%2,%3}, [%4];"
                 : "=r"(r0), "=r"(r1), "=r"(r2), "=r"(r3) : "r"(a));
}
__device__ __forceinline__ void MMA(float* d, u32 a0, u32 a1, u32 a2, u32 a3, u32 b0, u32 b1) {
    asm("mma.sync.aligned.m16n8k16.row.col.f32.bf16.bf16.f32 "
        "{%0,%1,%2,%3}, {%4,%5,%6,%7}, {%8,%9}, {%0,%1,%2,%3};"
        : "+f"(d[0]), "+f"(d[1]), "+f"(d[2]), "+f"(d[3])
        : "r"(a0), "r"(a1), "r"(a2), "r"(a3), "r"(b0), "r"(b1));
}
__device__ __forceinline__ void split2(float x, float y, u32& h, u32& l) {
    __nv_bfloat162 hb = __floats2bfloat162_rn(x, y);
    h = *reinterpret_cast<u32*>(&hb);
    float hx = __uint_as_float(h << 16), hy = __uint_as_float(h & 0xffff0000u);
    __nv_bfloat162 lb = __floats2bfloat162_rn(x - hx, y - hy);
    l = *reinterpret_cast<u32*>(&lb);
}
__device__ __forceinline__ u32 hi2(float x, float y) {
    __nv_bfloat162 hb = __floats2bfloat162_rn(x, y);
    return *reinterpret_cast<u32*>(&hb);
}
__device__ __forceinline__ float fexp(float x) {   // e^x via exp2 poly
    float t = fmaf(x, 1.442695041f, 12582912.0f);
    u32 ib = __float_as_uint(t) << 23;
    float f = fmaf(x, 1.442695041f, -(t - 12582912.0f));
    float p = fmaf(0.0096181291f, f, 0.0555041087f);
    p = fmaf(p, f, 0.2402265069f);
    p = fmaf(p, f, 0.6931471806f);
    p = fmaf(p, f, 1.0f);
    return __uint_as_float(__float_as_uint(p) + ib);
}

__global__ void pack_mask(const int4* __restrict__ m) {
    long idx = (long)blockIdx.x * 256 + threadIdx.x;
    int4 v = m[idx];
    u32 w = ((u32)(v.x != 0) | ((u32)(v.y != 0) << 1) |
             ((u32)(v.z != 0) << 2) | ((u32)(v.w != 0) << 3))
            << ((threadIdx.x & 7) * 4);
    w |= __shfl_xor_sync(0xffffffffu, w, 1);
    w |= __shfl_xor_sync(0xffffffffu, w, 2);
    w |= __shfl_xor_sync(0xffffffffu, w, 4);
    if ((threadIdx.x & 7) == 0) g_mask_bits[idx >> 3] = w;
}

// ---------------- rowsum (512 thr, 128 q-rows, 1-MMA bf16-hi) ----------------
__global__ void __launch_bounds__(512)
rowsum(const float* __restrict__ Q, const float* __restrict__ K)
{
    extern __shared__ char smem[];
    const u32 sb = smem_u32(smem);
    float* rs = (float*)(smem + RS_RS);

    const int tid = threadIdx.x, lane = tid & 31, wid = tid >> 5;
    const int wn = wid & 1, wm = wid >> 1;   // wm 0..7
    const int qt = blockIdx.x, h = blockIdx.y, b = blockIdx.z;
    const long bh = (long)b * 16 + h;
    const float* qb = Q + (bh * 2048 + (long)qt * 128) * 64;
    const float* kb = K + bh * 2048 * 64;

    const int d4 = (tid & 15) << 2, jb = tid >> 4;   // jb 0..31
    const int qlr = lane & 15, qlc = (lane >> 4) << 3;
    const int klr = ((lane >> 4) << 3) | (lane & 7), klc = ((lane >> 3) & 1) << 3;

    // Q (x0.125, hi only) -> smem (128 rows)
    #pragma unroll
    for (int t = 0; t < 4; ++t) {
        int i = jb + 32 * t;
        float4 qv = *(const float4*)(qb + (long)i * 64 + d4);
        *(u64*)(smem + RS_QH + i * STB + d4 * 2) =
            ((u64)hi2(qv.z * 0.125f, qv.w * 0.125f) << 32) | hi2(qv.x * 0.125f, qv.y * 0.125f);
    }

    const int lr = wm * 16 + (lane >> 2);            // 0..127
    const u32* mp0 = g_mask_bits + (((long)b * 2048 + qt * 128 + lr) << 6) + wn * 2;
    const u32* mp1 = mp0 + (8 << 6);
    float rsum0 = 0.f, rsum1 = 0.f;

    #pragma unroll 1
    for (int kt = 0; kt < 16; ++kt) {
        __syncthreads();
        #pragma unroll
        for (int t = 0; t < 4; ++t) {
            int j = jb + 32 * t;
            float4 kv = *(const float4*)(kb + (long)(kt * 128 + j) * 64 + d4);
            *(u64*)(smem + RS_KH + j * STB + d4 * 2) =
                ((u64)hi2(kv.z, kv.w) << 32) | hi2(kv.x, kv.y);
        }
        u32 mw00 = mp0[kt * 4], mw01 = mp0[kt * 4 + 1];
        u32 mw10 = mp1[kt * 4], mw11 = mp1[kt * 4 + 1];
        __syncthreads();

        float sacc[8][4];
        #pragma unroll
        for (int j = 0; j < 8; ++j)
            #pragma unroll
            for (int e = 0; e < 4; ++e) sacc[j][e] = 0.f;
        #pragma unroll
        for (int s = 0; s < 4; ++s) {
            u32 qh[4], kh[4][4];
            LDSM4(sb + RS_QH + (wm * 16 + qlr) * STB + (s * 16 + qlc) * 2,
                  qh[0], qh[1], qh[2], qh[3]);
            #pragma unroll
            for (int g = 0; g < 4; ++g)
                LDSM4(sb + RS_KH + (wn * 64 + g * 16 + klr) * STB + (s * 16 + klc) * 2,
                      kh[g][0], kh[g][1], kh[g][2], kh[g][3]);
            #pragma unroll
            for (int j = 0; j < 8; ++j) {
                int g = j >> 1, se = (j & 1) << 1;
                MMA(sacc[j], qh[0], qh[1], qh[2], qh[3], kh[g][se], kh[g][se + 1]);
            }
        }
        #pragma unroll
        for (int j = 0; j < 8; ++j) {
            int bit = (j * 8 + (lane & 3) * 2) & 31;
            u32 w0 = (j < 4) ? mw00 : mw01, w1 = (j < 4) ? mw10 : mw11;
            rsum0 += (((w0 >> bit) & 1u) ? fexp(sacc[j][0]) : 0.f)
                   + (((w0 >> (bit + 1)) & 1u) ? fexp(sacc[j][1]) : 0.f);
            rsum1 += (((w1 >> bit) & 1u) ? fexp(sacc[j][2]) : 0.f)
                   + (((w1 >> (bit + 1)) & 1u) ? fexp(sacc[j][3]) : 0.f);
        }
    }

    rsum0 += __shfl_xor_sync(0xffffffffu, rsum0, 1);
    rsum0 += __shfl_xor_sync(0xffffffffu, rsum0, 2);
    rsum1 += __shfl_xor_sync(0xffffffffu, rsum1, 1);
    rsum1 += __shfl_xor_sync(0xffffffffu, rsum1, 2);
    __syncthreads();
    if ((lane & 3) == 0) {
        rs[wn * 128 + lr] = rsum0;
        rs[wn * 128 + lr + 8] = rsum1;
    }
    __syncthreads();
    if (tid < 128)
        g_rowinv[bh * 2048 + qt * 128 + tid] = 1.0f / (rs[tid] + rs[128 + tid]);
}

// ---------------- main (512 thr, 128 q-rows): normalized attn + PV -> O ----------------
__global__ void __launch_bounds__(512)
attn_hmma(const float* __restrict__ Q, const float* __restrict__ K,
          const float* __restrict__ V, float* __restrict__ O, float* __restrict__ A)
{
    extern __shared__ char smem[];
    const u32 sb = smem_u32(smem);
    float* si = (float*)(smem + SI_OFF);

    const int tid = threadIdx.x, lane = tid & 31, wid = tid >> 5;
    const int wn = wid & 1, wm = wid >> 1;   // wm 0..7
    const int qt = blockIdx.x, h = blockIdx.y, b = blockIdx.z;
    const long bh = (long)b * 16 + h;
    const float* qb = Q + (bh * 2048 + (long)qt * 128) * 64;
    const float* kb = K + bh * 2048 * 64;
    const float* vb = V + bh * 2048 * 64;
    float* ob = O + (bh * 2048 + (long)qt * 128) * 64;
    float* ab = A + (bh * 2048 + (long)qt * 128) * 2048;

    const int d4 = (tid & 15) << 2, jb = tid >> 4;   // jb 0..31
    const int qlr = lane & 15, qlc = (lane >> 4) << 3;
    const int klr = ((lane >> 4) << 3) | (lane & 7), klc = ((lane >> 3) & 1) << 3;
    const int vlr = (((lane >> 3) & 1) << 3) | (lane & 7), vlc = (lane >> 4) << 3;

    if (tid < 128) si[tid] = g_rowinv[bh * 2048 + qt * 128 + tid];

    #pragma unroll
    for (int t = 0; t < 4; ++t) {
        int i = jb + 32 * t;
        float4 qv = *(const float4*)(qb + (long)i * 64 + d4);
        u32 h01, l01, h23, l23;
        split2(qv.x * 0.125f, qv.y * 0.125f, h01, l01);
        split2(qv.z * 0.125f, qv.w * 0.125f, h23, l23);
        *(u64*)(smem + QH_OFF + i * STB + d4 * 2) = ((u64)h23 << 32) | h01;
        *(u64*)(smem + QL_OFF + i * STB + d4 * 2) = ((u64)l23 << 32) | l01;
    }

    const int lr = wm * 16 + (lane >> 2);            // 0..127
    const u32* mp0 = g_mask_bits + (((long)b * 2048 + qt * 128 + lr) << 6) + wn * 2;
    const u32* mp1 = mp0 + (8 << 6);

    float oacc[8][4];
    #pragma unroll
    for (int dn = 0; dn < 8; ++dn)
        #pragma unroll
        for (int e = 0; e < 4; ++e) oacc[dn][e] = 0.f;

    #pragma unroll 1
    for (int kt = 0; kt < 16; ++kt) {
        __syncthreads();
        #pragma unroll
        for (int t = 0; t < 4; ++t) {
            int j = jb + 32 * t;
            long g = (long)(kt * 128 + j) * 64 + d4;
            float4 kv = *(const float4*)(kb + g);
            float4 vv = *(const float4*)(vb + g);
            u32 h01, l01, h23, l23;
            split2(kv.x, kv.y, h01, l01); split2(kv.z, kv.w, h23, l23);
            *(u64*)(smem + KH_OFF + j * STB + d4 * 2) = ((u64)h23 << 32) | h01;
            *(u64*)(smem + KL_OFF + j * STB + d4 * 2) = ((u64)l23 << 32) | l01;
            split2(vv.x, vv.y, h01, l01); split2(vv.z, vv.w, h23, l23);
            *(u64*)(smem + VH_OFF + j * STB + d4 * 2) = ((u64)h23 << 32) | h01;
            *(u64*)(smem + VL_OFF + j * STB + d4 * 2) = ((u64)l23 << 32) | l01;
        }
        u32 mw00 = mp0[kt * 4], mw01 = mp0[kt * 4 + 1];
        u32 mw10 = mp1[kt * 4], mw11 = mp1[kt * 4 + 1];
        __syncthreads();

        float sacc[8][4];
        #pragma unroll
        for (int j = 0; j < 8; ++j)
            #pragma unroll
            for (int e = 0; e < 4; ++e) sacc[j][e] = 0.f;
        #pragma unroll
        for (int s = 0; s < 4; ++s) {
            u32 qh[4], ql[4], kh[4][4], kl[4][4];
            u32 qa = sb + QH_OFF + (wm * 16 + qlr) * STB + (s * 16 + qlc) * 2;
            LDSM4(qa, qh[0], qh[1], qh[2], qh[3]);
            LDSM4(qa + (QL_OFF - QH_OFF), ql[0], ql[1], ql[2], ql[3]);
            #pragma unroll
            for (int g = 0; g < 4; ++g) {
                u32 ka = sb + KH_OFF + (wn * 64 + g * 16 + klr) * STB + (s * 16 + klc) * 2;
                LDSM4(ka, kh[g][0], kh[g][1], kh[g][2], kh[g][3]);
                LDSM4(ka + (KL_OFF - KH_OFF), kl[g][0], kl[g][1], kl[g][2], kl[g][3]);
            }
            #pragma unroll
            for (int j = 0; j < 8; ++j) {
                int g = j >> 1, se = (j & 1) << 1;
                MMA(sacc[j], qh[0], qh[1], qh[2], qh[3], kh[g][se], kh[g][se + 1]);
                MMA(sacc[j], ql[0], ql[1], ql[2], ql[3], kh[g][se], kh[g][se + 1]);
                MMA(sacc[j], qh[0], qh[1], qh[2], qh[3], kl[g][se], kl[g][se + 1]);
            }
        }

        const float iv0 = si[lr], iv1 = si[lr + 8];
        u32 psh[4][4], psl[4][4];
        #pragma unroll
        for (int j = 0; j < 8; ++j) {
            int bit = (j * 8 + (lane & 3) * 2) & 31;
            u32 w0 = (j < 4) ? mw00 : mw01, w1 = (j < 4) ? mw10 : mw11;
            float e0 = ((w0 >> bit) & 1u) ? fexp(sacc[j][0]) * iv0 : 0.f;
            float e1 = ((w0 >> (bit + 1)) & 1u) ? fexp(sacc[j][1]) * iv0 : 0.f;
            float e2 = ((w1 >> bit) & 1u) ? fexp(sacc[j][2]) * iv1 : 0.f;
            float e3 = ((w1 >> (bit + 1)) & 1u) ? fexp(sacc[j][3]) * iv1 : 0.f;
            long col = (long)kt * 128 + wn * 64 + j * 8 + (lane & 3) * 2;
            *(float2*)(ab + (long)lr * 2048 + col)       = make_float2(e0, e1);
            *(float2*)(ab + (long)(lr + 8) * 2048 + col) = make_float2(e2, e3);
            sacc[j][0] = e0; sacc[j][1] = e1; sacc[j][2] = e2; sacc[j][3] = e3;
        }
        #pragma unroll
        for (int jj = 0; jj < 4; ++jj) {
            split2(sacc[2 * jj][0],     sacc[2 * jj][1],     psh[jj][0], psl[jj][0]);
            split2(sacc[2 * jj][2],     sacc[2 * jj][3],     psh[jj][1], psl[jj][1]);
            split2(sacc[2 * jj + 1][0], sacc[2 * jj + 1][1], psh[jj][2], psl[jj][2]);
            split2(sacc[2 * jj + 1][2], sacc[2 * jj + 1][3], psh[jj][3], psl[jj][3]);
        }

        #pragma unroll
        for (int jj = 0; jj < 4; ++jj) {
            u32 vh[4][4], vl[4][4];
            #pragma unroll
            for (int g = 0; g < 4; ++g) {
                u32 va = sb + VH_OFF + (wn * 64 + jj * 16 + vlr) * STB + (g * 16 + vlc) * 2;
                LDSM4T(va, vh[g][0], vh[g][1], vh[g][2], vh[g][3]);
                LDSM4T(va + (VL_OFF - VH_OFF), vl[g][0], vl[g][1], vl[g][2], vl[g][3]);
            }
            #pragma unroll
            for (int dn = 0; dn < 8; ++dn) {
                int g = dn >> 1, se = (dn & 1) << 1;
                MMA(oacc[dn], psh[jj][0], psh[jj][1], psh[jj][2], psh[jj][3], vh[g][se], vh[g][se + 1]);
                MMA(oacc[dn], psl[jj][0], psl[jj][1], psl[jj][2], psl[jj][3], vh[g][se], vh[g][se + 1]);
                MMA(oacc[dn], psh[jj][0], psh[jj][1], psh[jj][2], psh[jj][3], vl[g][se], vl[g][se + 1]);
            }
        }
    }

    // ---- combine O halves (already normalized); osm 128x66 floats in Q region ----
    __syncthreads();
    float* osm = (float*)smem;
    if (wn == 1) {
        #pragma unroll
        for (int dn = 0; dn < 8; ++dn) {
            int c = dn * 8 + (lane & 3) * 2;
            *(float2*)&osm[lr * 66 + c]       = make_float2(oacc[dn][0], oacc[dn][1]);
            *(float2*)&osm[(lr + 8) * 66 + c] = make_float2(oacc[dn][2], oacc[dn][3]);
        }
    }
    __syncthreads();
    if (wn == 0) {
        #pragma unroll
        for (int dn = 0; dn < 8; ++dn) {
            int c = dn * 8 + (lane & 3) * 2;
            float2 p0 = *(float2*)&osm[lr * 66 + c];
            float2 p1 = *(float2*)&osm[(lr + 8) * 66 + c];
            *(float2*)(ob + (long)lr * 64 + c) =
                make_float2(oacc[dn][0] + p0.x, oacc[dn][1] + p0.y);
            *(float2*)(ob + (long)(lr + 8) * 64 + c) =
                make_float2(oacc[dn][2] + p1.x, oacc[dn][3] + p1.y);
        }
    }
}

extern "C" void kernel_launch(void* const* d_in, const int* in_sizes, int n_in,
                              void* d_out, int out_size) {
    const float* q = (const float*)d_in[0];
    const float* k = (const float*)d_in[1];
    const float* v = (const float*)d_in[2];
    const int* mask = (const int*)d_in[3];
    float* out = (float*)d_out;
    float* attn = out + (long)2 * 16 * 2048 * 64;

    cudaFuncSetAttribute(rowsum, cudaFuncAttributeMaxDynamicSharedMemorySize, RS_TOTAL);
    cudaFuncSetAttribute(attn_hmma, cudaFuncAttributeMaxDynamicSharedMemorySize, SM_TOTAL);
    pack_mask<<<(2L * 2048 * 2048 / 4) / 256, 256>>>((const int4*)mask);
    rowsum<<<dim3(16, 16, 2), 512, RS_TOTAL>>>(q, k);
    attn_hmma<<<dim3(16, 16, 2), 512, SM_TOTAL>>>(q, k, v, out, attn);
}

// round 15
// speedup vs baseline: 1.0304x; 1.0304x over previous
#include <cuda_runtime.h>
#include <cuda_bf16.h>

typedef unsigned int u32;
typedef unsigned long long u64;

// B=2,H=16,S=2048,D=64. d_out = [output | attn].
// k0 pack_mask (int4); k1 rowsum (1-MMA bf16-hi, 3 CTAs/SM) -> g_rowlg=-log2(sum);
// k2 main (r13 structure, exp2-domain: sacc init = rowlg -> normalized attn
//     written once, PV 3-MMA -> O).

#define STB 144
// main kernel smem
#define QH_OFF 0
#define QL_OFF 9216
#define KH_OFF 18432
#define KL_OFF 36864
#define VH_OFF 55296
#define VL_OFF 73728
#define SI_OFF 92160
#define SM_TOTAL 92416
// rowsum smem
#define RS_QH 0
#define RS_KH 9216
#define RS_RS 27648
#define RS_TOTAL 28160

__device__ u32 g_mask_bits[2 * 2048 * 64];
__device__ float g_rowlg[2 * 16 * 2048];

__device__ __forceinline__ u32 smem_u32(const void* p) {
    u32 a;
    asm("{ .reg .u64 t; cvta.to.shared.u64 t, %1; cvt.u32.u64 %0, t; }" : "=r"(a) : "l"(p));
    return a;
}
__device__ __forceinline__ void LDSM4(u32 a, u32& r0, u32& r1, u32& r2, u32& r3) {
    asm volatile("ldmatrix.sync.aligned.m8n8.x4.shared.b16 {%0,%1,%2,%3}, [%4];"
                 : "=r"(r0), "=r"(r1), "=r"(r2), "=r"(r3) : "r"(a));
}
__device__ __forceinline__ void LDSM4T(u32 a, u32& r0, u32& r1, u32& r2, u32& r3) {
    asm volatile("ldmatrix.sync.aligned.m8n8.x4.trans.shared.b16 {%0,%1,%2,%3}, [%4];"
                 : "=r"(r0), "=r"(r1), "=r"(r2), "=r"(r3) : "r"(a));
}
__device__ __forceinline__ void MMA(float* d, u32 a0, u32 a1, u32 a2, u32 a3, u32 b0, u32 b1) {
    asm("mma.sync.aligned.m16n8k16.row.col.f32.bf16.bf16.f32 "
        "{%0,%1,%2,%3}, {%4,%5,%6,%7}, {%8,%9}, {%0,%1,%2,%3};"
        : "+f"(d[0]), "+f"(d[1]), "+f"(d[2]), "+f"(d[3])
        : "r"(a0), "r"(a1), "r"(a2), "r"(a3), "r"(b0), "r"(b1));
}
__device__ __forceinline__ void split2(float x, float y, u32& h, u32& l) {
    __nv_bfloat162 hb = __floats2bfloat162_rn(x, y);
    h = *reinterpret_cast<u32*>(&hb);
    float hx = __uint_as_float(h << 16), hy = __uint_as_float(h & 0xffff0000u);
    __nv_bfloat162 lb = __floats2bfloat162_rn(x - hx, y - hy);
    l = *reinterpret_cast<u32*>(&lb);
}
__device__ __forceinline__ u32 hi2(float x, float y) {
    __nv_bfloat162 hb = __floats2bfloat162_rn(x, y);
    return *reinterpret_cast<u32*>(&hb);
}
__device__ __forceinline__ float fexp(float x) {   // e^x
    float t = fmaf(x, 1.442695041f, 12582912.0f);
    u32 ib = __float_as_uint(t) << 23;
    float f = fmaf(x, 1.442695041f, -(t - 12582912.0f));
    float p = fmaf(0.0096181291f, f, 0.0555041087f);
    p = fmaf(p, f, 0.2402265069f);
    p = fmaf(p, f, 0.6931471806f);
    p = fmaf(p, f, 1.0f);
    return __uint_as_float(__float_as_uint(p) + ib);
}
__device__ __forceinline__ float fexp2(float x) {   // 2^x
    float t = x + 12582912.0f;
    u32 ib = __float_as_uint(t) << 23;
    float f = x - (t - 12582912.0f);
    float p = fmaf(1.3328521e-3f, f, 9.6181291e-3f);
    p = fmaf(p, f, 5.5504109e-2f);
    p = fmaf(p, f, 2.4022651e-1f);
    p = fmaf(p, f, 6.9314718e-1f);
    p = fmaf(p, f, 1.0f);
    return __uint_as_float(__float_as_uint(p) + ib);
}

__global__ void pack_mask(const int4* __restrict__ m) {
    long idx = (long)blockIdx.x * 256 + threadIdx.x;
    int4 v = m[idx];
    u32 w = ((u32)(v.x != 0) | ((u32)(v.y != 0) << 1) |
             ((u32)(v.z != 0) << 2) | ((u32)(v.w != 0) << 3))
            << ((threadIdx.x & 7) * 4);
    w |= __shfl_xor_sync(0xffffffffu, w, 1);
    w |= __shfl_xor_sync(0xffffffffu, w, 2);
    w |= __shfl_xor_sync(0xffffffffu, w, 4);
    if ((threadIdx.x & 7) == 0) g_mask_bits[idx >> 3] = w;
}

// ---------------- rowsum (1-MMA bf16-hi, 3 CTAs/SM) -> g_rowlg ----------------
__global__ void __launch_bounds__(256, 3)
rowsum(const float* __restrict__ Q, const float* __restrict__ K)
{
    extern __shared__ char smem[];
    const u32 sb = smem_u32(smem);
    float* rs = (float*)(smem + RS_RS);

    const int tid = threadIdx.x, lane = tid & 31, wid = tid >> 5;
    const int wn = wid & 1, wm = wid >> 1;
    const int qt = blockIdx.x, h = blockIdx.y, b = blockIdx.z;
    const long bh = (long)b * 16 + h;
    const float* qb = Q + (bh * 2048 + (long)qt * 64) * 64;
    const float* kb = K + bh * 2048 * 64;

    const int d4 = (tid & 15) << 2, jb = tid >> 4;
    const int qlr = lane & 15, qlc = (lane >> 4) << 3;
    const int klr = ((lane >> 4) << 3) | (lane & 7), klc = ((lane >> 3) & 1) << 3;

    #pragma unroll
    for (int t = 0; t < 4; ++t) {
        int i = jb + 16 * t;
        float4 qv = *(const float4*)(qb + (long)i * 64 + d4);
        *(u64*)(smem + RS_QH + i * STB + d4 * 2) =
            ((u64)hi2(qv.z * 0.125f, qv.w * 0.125f) << 32) | hi2(qv.x * 0.125f, qv.y * 0.125f);
    }

    const int lr = wm * 16 + (lane >> 2);
    const u32* mp0 = g_mask_bits + (((long)b * 2048 + qt * 64 + lr) << 6) + wn * 2;
    const u32* mp1 = mp0 + (8 << 6);
    float rsum0 = 0.f, rsum1 = 0.f;

    #pragma unroll 1
    for (int kt = 0; kt < 16; ++kt) {
        __syncthreads();
        #pragma unroll
        for (int t = 0; t < 8; ++t) {
            int j = jb + 16 * t;
            float4 kv = *(const float4*)(kb + (long)(kt * 128 + j) * 64 + d4);
            *(u64*)(smem + RS_KH + j * STB + d4 * 2) =
                ((u64)hi2(kv.z, kv.w) << 32) | hi2(kv.x, kv.y);
        }
        u32 mw00 = mp0[kt * 4], mw01 = mp0[kt * 4 + 1];
        u32 mw10 = mp1[kt * 4], mw11 = mp1[kt * 4 + 1];
        __syncthreads();

        float sacc[8][4];
        #pragma unroll
        for (int j = 0; j < 8; ++j)
            #pragma unroll
            for (int e = 0; e < 4; ++e) sacc[j][e] = 0.f;
        #pragma unroll
        for (int s = 0; s < 4; ++s) {
            u32 qh[4], kh[4][4];
            LDSM4(sb + RS_QH + (wm * 16 + qlr) * STB + (s * 16 + qlc) * 2,
                  qh[0], qh[1], qh[2], qh[3]);
            #pragma unroll
            for (int g = 0; g < 4; ++g)
                LDSM4(sb + RS_KH + (wn * 64 + g * 16 + klr) * STB + (s * 16 + klc) * 2,
                      kh[g][0], kh[g][1], kh[g][2], kh[g][3]);
            #pragma unroll
            for (int j = 0; j < 8; ++j) {
                int g = j >> 1, se = (j & 1) << 1;
                MMA(sacc[j], qh[0], qh[1], qh[2], qh[3], kh[g][se], kh[g][se + 1]);
            }
        }
        #pragma unroll
        for (int j = 0; j < 8; ++j) {
            int bit = (j * 8 + (lane & 3) * 2) & 31;
            u32 w0 = (j < 4) ? mw00 : mw01, w1 = (j < 4) ? mw10 : mw11;
            rsum0 += (((w0 >> bit) & 1u) ? fexp(sacc[j][0]) : 0.f)
                   + (((w0 >> (bit + 1)) & 1u) ? fexp(sacc[j][1]) : 0.f);
            rsum1 += (((w1 >> bit) & 1u) ? fexp(sacc[j][2]) : 0.f)
                   + (((w1 >> (bit + 1)) & 1u) ? fexp(sacc[j][3]) : 0.f);
        }
    }

    rsum0 += __shfl_xor_sync(0xffffffffu, rsum0, 1);
    rsum0 += __shfl_xor_sync(0xffffffffu, rsum0, 2);
    rsum1 += __shfl_xor_sync(0xffffffffu, rsum1, 1);
    rsum1 += __shfl_xor_sync(0xffffffffu, rsum1, 2);
    __syncthreads();
    if ((lane & 3) == 0) {
        rs[wn * 64 + lr] = rsum0;
        rs[wn * 64 + lr + 8] = rsum1;
    }
    __syncthreads();
    if (tid < 64)
        g_rowlg[bh * 2048 + qt * 64 + tid] = -__log2f(rs[tid] + rs[64 + tid]);
}

// ---------------- main: exp2-domain normalized attn + PV -> O ----------------
__global__ void __launch_bounds__(256)
attn_hmma(const float* __restrict__ Q, const float* __restrict__ K,
          const float* __restrict__ V, float* __restrict__ O, float* __restrict__ A)
{
    extern __shared__ char smem[];
    const u32 sb = smem_u32(smem);
    float* si = (float*)(smem + SI_OFF);

    const int tid = threadIdx.x, lane = tid & 31, wid = tid >> 5;
    const int wn = wid & 1, wm = wid >> 1;
    const int qt = blockIdx.x, h = blockIdx.y, b = blockIdx.z;
    const long bh = (long)b * 16 + h;
    const float* qb = Q + (bh * 2048 + (long)qt * 64) * 64;
    const float* kb = K + bh * 2048 * 64;
    const float* vb = V + bh * 2048 * 64;
    float* ob = O + (bh * 2048 + (long)qt * 64) * 64;
    float* ab = A + (bh * 2048 + (long)qt * 64) * 2048;

    const int d4 = (tid & 15) << 2, jb = tid >> 4;
    const int qlr = lane & 15, qlc = (lane >> 4) << 3;
    const int klr = ((lane >> 4) << 3) | (lane & 7), klc = ((lane >> 3) & 1) << 3;
    const int vlr = (((lane >> 3) & 1) << 3) | (lane & 7), vlc = (lane >> 4) << 3;

    if (tid < 64) si[tid] = g_rowlg[bh * 2048 + qt * 64 + tid];

    const float QS = 0.18033688011112042f;   // 0.125 * log2(e)
    #pragma unroll
    for (int t = 0; t < 4; ++t) {
        int i = jb + 16 * t;
        float4 qv = *(const float4*)(qb + (long)i * 64 + d4);
        u32 h01, l01, h23, l23;
        split2(qv.x * QS, qv.y * QS, h01, l01);
        split2(qv.z * QS, qv.w * QS, h23, l23);
        *(u64*)(smem + QH_OFF + i * STB + d4 * 2) = ((u64)h23 << 32) | h01;
        *(u64*)(smem + QL_OFF + i * STB + d4 * 2) = ((u64)l23 << 32) | l01;
    }

    const int lr = wm * 16 + (lane >> 2);
    const u32* mp0 = g_mask_bits + (((long)b * 2048 + qt * 64 + lr) << 6) + wn * 2;
    const u32* mp1 = mp0 + (8 << 6);

    float oacc[8][4];
    #pragma unroll
    for (int dn = 0; dn < 8; ++dn)
        #pragma unroll
        for (int e = 0; e < 4; ++e) oacc[dn][e] = 0.f;

    #pragma unroll 1
    for (int kt = 0; kt < 16; ++kt) {
        __syncthreads();
        #pragma unroll
        for (int t = 0; t < 8; ++t) {
            int j = jb + 16 * t;
            long g = (long)(kt * 128 + j) * 64 + d4;
            float4 kv = *(const float4*)(kb + g);
            float4 vv = *(const float4*)(vb + g);
            u32 h01, l01, h23, l23;
            split2(kv.x, kv.y, h01, l01); split2(kv.z, kv.w, h23, l23);
            *(u64*)(smem + KH_OFF + j * STB + d4 * 2) = ((u64)h23 << 32) | h01;
            *(u64*)(smem + KL_OFF + j * STB + d4 * 2) = ((u64)l23 << 32) | l01;
            split2(vv.x, vv.y, h01, l01); split2(vv.z, vv.w, h23, l23);
            *(u64*)(smem + VH_OFF + j * STB + d4 * 2) = ((u64)h23 << 32) | h01;
            *(u64*)(smem + VL_OFF + j * STB + d4 * 2) = ((u64)l23 << 32) | l01;
        }
        u32 mw00 = mp0[kt * 4], mw01 = mp0[kt * 4 + 1];
        u32 mw10 = mp1[kt * 4], mw11 = mp1[kt * 4 + 1];
        __syncthreads();

        const float L0 = si[lr], L1 = si[lr + 8];
        float sacc[8][4];
        #pragma unroll
        for (int j = 0; j < 8; ++j) {
            sacc[j][0] = L0; sacc[j][1] = L0;
            sacc[j][2] = L1; sacc[j][3] = L1;
        }
        #pragma unroll
        for (int s = 0; s < 4; ++s) {
            u32 qh[4], ql[4], kh[4][4], kl[4][4];
            u32 qa = sb + QH_OFF + (wm * 16 + qlr) * STB + (s * 16 + qlc) * 2;
            LDSM4(qa, qh[0], qh[1], qh[2], qh[3]);
            LDSM4(qa + (QL_OFF - QH_OFF), ql[0], ql[1], ql[2], ql[3]);
            #pragma unroll
            for (int g = 0; g < 4; ++g) {
                u32 ka = sb + KH_OFF + (wn * 64 + g * 16 + klr) * STB + (s * 16 + klc) * 2;
                LDSM4(ka, kh[g][0], kh[g][1], kh[g][2], kh[g][3]);
                LDSM4(ka + (KL_OFF - KH_OFF), kl[g][0], kl[g][1], kl[g][2], kl[g][3]);
            }
            #pragma unroll
            for (int j = 0; j < 8; ++j) {
                int g = j >> 1, se = (j & 1) << 1;
                MMA(sacc[j], qh[0], qh[1], qh[2], qh[3], kh[g][se], kh[g][se + 1]);
                MMA(sacc[j], ql[0], ql[1], ql[2], ql[3], kh[g][se], kh[g][se + 1]);
                MMA(sacc[j], qh[0], qh[1], qh[2], qh[3], kl[g][se], kl[g][se + 1]);
            }
        }

        // epilogue: p = 2^(s + rowlg) (normalized); mask; STG; split -> P frags
        u32 psh[4][4], psl[4][4];
        #pragma unroll
        for (int j = 0; j < 8; ++j) {
            int bit = (j * 8 + (lane & 3) * 2) & 31;
            u32 w0 = (j < 4) ? mw00 : mw01, w1 = (j < 4) ? mw10 : mw11;
            float e0 = ((w0 >> bit) & 1u) ? fexp2(sacc[j][0]) : 0.f;
            float e1 = ((w0 >> (bit + 1)) & 1u) ? fexp2(sacc[j][1]) : 0.f;
            float e2 = ((w1 >> bit) & 1u) ? fexp2(sacc[j][2]) : 0.f;
            float e3 = ((w1 >> (bit + 1)) & 1u) ? fexp2(sacc[j][3]) : 0.f;
            long col = (long)kt * 128 + wn * 64 + j * 8 + (lane & 3) * 2;
            *(float2*)(ab + (long)lr * 2048 + col)       = make_float2(e0, e1);
            *(float2*)(ab + (long)(lr + 8) * 2048 + col) = make_float2(e2, e3);
            sacc[j][0] = e0; sacc[j][1] = e1; sacc[j][2] = e2; sacc[j][3] = e3;
        }
        #pragma unroll
        for (int jj = 0; jj < 4; ++jj) {
            split2(sacc[2 * jj][0],     sacc[2 * jj][1],     psh[jj][0], psl[jj][0]);
            split2(sacc[2 * jj][2],     sacc[2 * jj][3],     psh[jj][1], psl[jj][1]);
            split2(sacc[2 * jj + 1][0], sacc[2 * jj + 1][1], psh[jj][2], psl[jj][2]);
            split2(sacc[2 * jj + 1][2], sacc[2 * jj + 1][3], psh[jj][3], psl[jj][3]);
        }

        #pragma unroll
        for (int jj = 0; jj < 4; ++jj) {
            u32 vh[4][4], vl[4][4];
            #pragma unroll
            for (int g = 0; g < 4; ++g) {
                u32 va = sb + VH_OFF + (wn * 64 + jj * 16 + vlr) * STB + (g * 16 + vlc) * 2;
                LDSM4T(va, vh[g][0], vh[g][1], vh[g][2], vh[g][3]);
                LDSM4T(va + (VL_OFF - VH_OFF), vl[g][0], vl[g][1], vl[g][2], vl[g][3]);
            }
            #pragma unroll
            for (int dn = 0; dn < 8; ++dn) {
                int g = dn >> 1, se = (dn & 1) << 1;
                MMA(oacc[dn], psh[jj][0], psh[jj][1], psh[jj][2], psh[jj][3], vh[g][se], vh[g][se + 1]);
                MMA(oacc[dn], psl[jj][0], psl[jj][1], psl[jj][2], psl[jj][3], vh[g][se], vh[g][se + 1]);
                MMA(oacc[dn], psh[jj][0], psh[jj][1], psh[jj][2], psh[jj][3], vl[g][se], vl[g][se + 1]);
            }
        }
    }

    __syncthreads();
    float* osm = (float*)smem;
    if (wn == 1) {
        #pragma unroll
        for (int dn = 0; dn < 8; ++dn) {
            int c = dn * 8 + (lane & 3) * 2;
            *(float2*)&osm[lr * 66 + c]       = make_float2(oacc[dn][0], oacc[dn][1]);
            *(float2*)&osm[(lr + 8) * 66 + c] = make_float2(oacc[dn][2], oacc[dn][3]);
        }
    }
    __syncthreads();
    if (wn == 0) {
        #pragma unroll
        for (int dn = 0; dn < 8; ++dn) {
            int c = dn * 8 + (lane & 3) * 2;
            float2 p0 = *(float2*)&osm[lr * 66 + c];
            float2 p1 = *(float2*)&osm[(lr + 8) * 66 + c];
            *(float2*)(ob + (long)lr * 64 + c) =
                make_float2(oacc[dn][0] + p0.x, oacc[dn][1] + p0.y);
            *(float2*)(ob + (long)(lr + 8) * 64 + c) =
                make_float2(oacc[dn][2] + p1.x, oacc[dn][3] + p1.y);
        }
    }
}

extern "C" void kernel_launch(void* const* d_in, const int* in_sizes, int n_in,
                              void* d_out, int out_size) {
    const float* q = (const float*)d_in[0];
    const float* k = (const float*)d_in[1];
    const float* v = (const float*)d_in[2];
    const int* mask = (const int*)d_in[3];
    float* out = (float*)d_out;
    float* attn = out + (long)2 * 16 * 2048 * 64;

    cudaFuncSetAttribute(rowsum, cudaFuncAttributeMaxDynamicSharedMemorySize, RS_TOTAL);
    cudaFuncSetAttribute(attn_hmma, cudaFuncAttributeMaxDynamicSharedMemorySize, SM_TOTAL);
    pack_mask<<<(2L * 2048 * 2048 / 4) / 256, 256>>>((const int4*)mask);
    rowsum<<<dim3(32, 16, 2), 256, RS_TOTAL>>>(q, k);
    attn_hmma<<<dim3(32, 16, 2), 256, SM_TOTAL>>>(q, k, v, out, attn);
}

// round 16
// speedup vs baseline: 1.1748x; 1.1401x over previous
#include <cuda_runtime.h>
#include <cuda_bf16.h>

typedef unsigned int u32;
typedef unsigned long long u64;

// B=2,H=16,S=2048,D=64. d_out = [output | attn].
// k0 pack_mask (int4); k1 rowsum (1-MMA bf16-hi, exp2-domain deg-3, 3 CTAs/SM)
//     -> g_rowlg = -log2(sum);
// k2 main (exp2-domain, sacc init = rowlg -> normalized attn once, PV 3-MMA -> O).

#define STB 144
// main kernel smem
#define QH_OFF 0
#define QL_OFF 9216
#define KH_OFF 18432
#define KL_OFF 36864
#define VH_OFF 55296
#define VL_OFF 73728
#define SI_OFF 92160
#define SM_TOTAL 92416
// rowsum smem
#define RS_QH 0
#define RS_KH 9216
#define RS_RS 27648
#define RS_TOTAL 28160

__device__ u32 g_mask_bits[2 * 2048 * 64];
__device__ float g_rowlg[2 * 16 * 2048];

__device__ __forceinline__ u32 smem_u32(const void* p) {
    u32 a;
    asm("{ .reg .u64 t; cvta.to.shared.u64 t, %1; cvt.u32.u64 %0, t; }" : "=r"(a) : "l"(p));
    return a;
}
__device__ __forceinline__ void LDSM4(u32 a, u32& r0, u32& r1, u32& r2, u32& r3) {
    asm volatile("ldmatrix.sync.aligned.m8n8.x4.shared.b16 {%0,%1,%2,%3}, [%4];"
                 : "=r"(r0), "=r"(r1), "=r"(r2), "=r"(r3) : "r"(a));
}
__device__ __forceinline__ void LDSM4T(u32 a, u32& r0, u32& r1, u32& r2, u32& r3) {
    asm volatile("ldmatrix.sync.aligned.m8n8.x4.trans.shared.b16 {%0,%1,%2,%3}, [%4];"
                 : "=r"(r0), "=r"(r1), "=r"(r2), "=r"(r3) : "r"(a));
}
__device__ __forceinline__ void MMA(float* d, u32 a0, u32 a1, u32 a2, u32 a3, u32 b0, u32 b1) {
    asm("mma.sync.aligned.m16n8k16.row.col.f32.bf16.bf16.f32 "
        "{%0,%1,%2,%3}, {%4,%5,%6,%7}, {%8,%9}, {%0,%1,%2,%3};"
        : "+f"(d[0]), "+f"(d[1]), "+f"(d[2]), "+f"(d[3])
        : "r"(a0), "r"(a1), "r"(a2), "r"(a3), "r"(b0), "r"(b1));
}
__device__ __forceinline__ void split2(float x, float y, u32& h, u32& l) {
    __nv_bfloat162 hb = __floats2bfloat162_rn(x, y);
    h = *reinterpret_cast<u32*>(&hb);
    float hx = __uint_as_float(h << 16), hy = __uint_as_float(h & 0xffff0000u);
    __nv_bfloat162 lb = __floats2bfloat162_rn(x - hx, y - hy);
    l = *reinterpret_cast<u32*>(&lb);
}
__device__ __forceinline__ u32 hi2(float x, float y) {
    __nv_bfloat162 hb = __floats2bfloat162_rn(x, y);
    return *reinterpret_cast<u32*>(&hb);
}
__device__ __forceinline__ float fexp2_4(float x) {   // 2^x, deg-4, rel err <= 4e-5
    float t = x + 12582912.0f;
    u32 ib = __float_as_uint(t) << 23;
    float f = x - (t - 12582912.0f);
    float p = fmaf(9.6181291e-3f, f, 5.5504109e-2f);
    p = fmaf(p, f, 2.4022651e-1f);
    p = fmaf(p, f, 6.9314718e-1f);
    p = fmaf(p, f, 1.0f);
    return __uint_as_float(__float_as_uint(p) + ib);
}
__device__ __forceinline__ float fexp2_3(float x) {   // 2^x, deg-3 centered (sum use)
    float t = x + 12582912.0f;
    u32 ib = __float_as_uint(t) << 23;
    float f = x - (t - 12582912.0f);
    float p = fmaf(5.5504109e-2f, f, 2.4022651e-1f);
    p = fmaf(p, f, 6.9314718e-1f);
    p = fmaf(p, f, 0.99988f);        // c0 lowered to null Taylor-error bias
    return __uint_as_float(__float_as_uint(p) + ib);
}

__global__ void pack_mask(const int4* __restrict__ m) {
    long idx = (long)blockIdx.x * 256 + threadIdx.x;
    int4 v = m[idx];
    u32 w = ((u32)(v.x != 0) | ((u32)(v.y != 0) << 1) |
             ((u32)(v.z != 0) << 2) | ((u32)(v.w != 0) << 3))
            << ((threadIdx.x & 7) * 4);
    w |= __shfl_xor_sync(0xffffffffu, w, 1);
    w |= __shfl_xor_sync(0xffffffffu, w, 2);
    w |= __shfl_xor_sync(0xffffffffu, w, 4);
    if ((threadIdx.x & 7) == 0) g_mask_bits[idx >> 3] = w;
}

// ---------------- rowsum (1-MMA bf16-hi, exp2 domain) -> g_rowlg ----------------
__global__ void __launch_bounds__(256, 3)
rowsum(const float* __restrict__ Q, const float* __restrict__ K)
{
    extern __shared__ char smem[];
    const u32 sb = smem_u32(smem);
    float* rs = (float*)(smem + RS_RS);

    const int tid = threadIdx.x, lane = tid & 31, wid = tid >> 5;
    const int wn = wid & 1, wm = wid >> 1;
    const int qt = blockIdx.x, h = blockIdx.y, b = blockIdx.z;
    const long bh = (long)b * 16 + h;
    const float* qb = Q + (bh * 2048 + (long)qt * 64) * 64;
    const float* kb = K + bh * 2048 * 64;

    const int d4 = (tid & 15) << 2, jb = tid >> 4;
    const int qlr = lane & 15, qlc = (lane >> 4) << 3;
    const int klr = ((lane >> 4) << 3) | (lane & 7), klc = ((lane >> 3) & 1) << 3;

    const float QS = 0.18033688011112042f;   // 0.125 * log2(e)
    #pragma unroll
    for (int t = 0; t < 4; ++t) {
        int i = jb + 16 * t;
        float4 qv = *(const float4*)(qb + (long)i * 64 + d4);
        *(u64*)(smem + RS_QH + i * STB + d4 * 2) =
            ((u64)hi2(qv.z * QS, qv.w * QS) << 32) | hi2(qv.x * QS, qv.y * QS);
    }

    const int lr = wm * 16 + (lane >> 2);
    const u64* mp0 = (const u64*)(g_mask_bits + (((long)b * 2048 + qt * 64 + lr) << 6) + wn * 2);
    const u64* mp1 = (const u64*)((const u32*)mp0 + (8 << 6));
    float rsum0 = 0.f, rsum1 = 0.f;

    #pragma unroll 1
    for (int kt = 0; kt < 16; ++kt) {
        __syncthreads();
        #pragma unroll
        for (int t = 0; t < 8; ++t) {
            int j = jb + 16 * t;
            float4 kv = *(const float4*)(kb + (long)(kt * 128 + j) * 64 + d4);
            *(u64*)(smem + RS_KH + j * STB + d4 * 2) =
                ((u64)hi2(kv.z, kv.w) << 32) | hi2(kv.x, kv.y);
        }
        u64 m0 = mp0[kt * 2], m1 = mp1[kt * 2];
        u32 mw00 = (u32)m0, mw01 = (u32)(m0 >> 32);
        u32 mw10 = (u32)m1, mw11 = (u32)(m1 >> 32);
        __syncthreads();

        float sacc[8][4];
        #pragma unroll
        for (int j = 0; j < 8; ++j)
            #pragma unroll
            for (int e = 0; e < 4; ++e) sacc[j][e] = 0.f;
        #pragma unroll
        for (int s = 0; s < 4; ++s) {
            u32 qh[4], kh[4][4];
            LDSM4(sb + RS_QH + (wm * 16 + qlr) * STB + (s * 16 + qlc) * 2,
                  qh[0], qh[1], qh[2], qh[3]);
            #pragma unroll
            for (int g = 0; g < 4; ++g)
                LDSM4(sb + RS_KH + (wn * 64 + g * 16 + klr) * STB + (s * 16 + klc) * 2,
                      kh[g][0], kh[g][1], kh[g][2], kh[g][3]);
            #pragma unroll
            for (int j = 0; j < 8; ++j) {
                int g = j >> 1, se = (j & 1) << 1;
                MMA(sacc[j], qh[0], qh[1], qh[2], qh[3], kh[g][se], kh[g][se + 1]);
            }
        }
        #pragma unroll
        for (int j = 0; j < 8; ++j) {
            int bit = (j * 8 + (lane & 3) * 2) & 31;
            u32 w0 = (j < 4) ? mw00 : mw01, w1 = (j < 4) ? mw10 : mw11;
            rsum0 += (((w0 >> bit) & 1u) ? fexp2_3(sacc[j][0]) : 0.f)
                   + (((w0 >> (bit + 1)) & 1u) ? fexp2_3(sacc[j][1]) : 0.f);
            rsum1 += (((w1 >> bit) & 1u) ? fexp2_3(sacc[j][2]) : 0.f)
                   + (((w1 >> (bit + 1)) & 1u) ? fexp2_3(sacc[j][3]) : 0.f);
        }
    }

    rsum0 += __shfl_xor_sync(0xffffffffu, rsum0, 1);
    rsum0 += __shfl_xor_sync(0xffffffffu, rsum0, 2);
    rsum1 += __shfl_xor_sync(0xffffffffu, rsum1, 1);
    rsum1 += __shfl_xor_sync(0xffffffffu, rsum1, 2);
    __syncthreads();
    if ((lane & 3) == 0) {
        rs[wn * 64 + lr] = rsum0;
        rs[wn * 64 + lr + 8] = rsum1;
    }
    __syncthreads();
    if (tid < 64)
        g_rowlg[bh * 2048 + qt * 64 + tid] = -__log2f(rs[tid] + rs[64 + tid]);
}

// ---------------- main: exp2-domain normalized attn + PV -> O ----------------
__global__ void __launch_bounds__(256)
attn_hmma(const float* __restrict__ Q, const float* __restrict__ K,
          const float* __restrict__ V, float* __restrict__ O, float* __restrict__ A)
{
    extern __shared__ char smem[];
    const u32 sb = smem_u32(smem);
    float* si = (float*)(smem + SI_OFF);

    const int tid = threadIdx.x, lane = tid & 31, wid = tid >> 5;
    const int wn = wid & 1, wm = wid >> 1;
    const int qt = blockIdx.x, h = blockIdx.y, b = blockIdx.z;
    const long bh = (long)b * 16 + h;
    const float* qb = Q + (bh * 2048 + (long)qt * 64) * 64;
    const float* kb = K + bh * 2048 * 64;
    const float* vb = V + bh * 2048 * 64;
    float* ob = O + (bh * 2048 + (long)qt * 64) * 64;
    float* ab = A + (bh * 2048 + (long)qt * 64) * 2048;

    const int d4 = (tid & 15) << 2, jb = tid >> 4;
    const int qlr = lane & 15, qlc = (lane >> 4) << 3;
    const int klr = ((lane >> 4) << 3) | (lane & 7), klc = ((lane >> 3) & 1) << 3;
    const int vlr = (((lane >> 3) & 1) << 3) | (lane & 7), vlc = (lane >> 4) << 3;

    if (tid < 64) si[tid] = g_rowlg[bh * 2048 + qt * 64 + tid];

    const float QS = 0.18033688011112042f;   // 0.125 * log2(e)
    #pragma unroll
    for (int t = 0; t < 4; ++t) {
        int i = jb + 16 * t;
        float4 qv = *(const float4*)(qb + (long)i * 64 + d4);
        u32 h01, l01, h23, l23;
        split2(qv.x * QS, qv.y * QS, h01, l01);
        split2(qv.z * QS, qv.w * QS, h23, l23);
        *(u64*)(smem + QH_OFF + i * STB + d4 * 2) = ((u64)h23 << 32) | h01;
        *(u64*)(smem + QL_OFF + i * STB + d4 * 2) = ((u64)l23 << 32) | l01;
    }

    const int lr = wm * 16 + (lane >> 2);
    const u64* mp0 = (const u64*)(g_mask_bits + (((long)b * 2048 + qt * 64 + lr) << 6) + wn * 2);
    const u64* mp1 = (const u64*)((const u32*)mp0 + (8 << 6));

    float oacc[8][4];
    #pragma unroll
    for (int dn = 0; dn < 8; ++dn)
        #pragma unroll
        for (int e = 0; e < 4; ++e) oacc[dn][e] = 0.f;

    #pragma unroll 1
    for (int kt = 0; kt < 16; ++kt) {
        __syncthreads();
        #pragma unroll
        for (int t = 0; t < 8; ++t) {
            int j = jb + 16 * t;
            long g = (long)(kt * 128 + j) * 64 + d4;
            float4 kv = *(const float4*)(kb + g);
            float4 vv = *(const float4*)(vb + g);
            u32 h01, l01, h23, l23;
            split2(kv.x, kv.y, h01, l01); split2(kv.z, kv.w, h23, l23);
            *(u64*)(smem + KH_OFF + j * STB + d4 * 2) = ((u64)h23 << 32) | h01;
            *(u64*)(smem + KL_OFF + j * STB + d4 * 2) = ((u64)l23 << 32) | l01;
            split2(vv.x, vv.y, h01, l01); split2(vv.z, vv.w, h23, l23);
            *(u64*)(smem + VH_OFF + j * STB + d4 * 2) = ((u64)h23 << 32) | h01;
            *(u64*)(smem + VL_OFF + j * STB + d4 * 2) = ((u64)l23 << 32) | l01;
        }
        u64 m0 = mp0[kt * 2], m1 = mp1[kt * 2];
        u32 mw00 = (u32)m0, mw01 = (u32)(m0 >> 32);
        u32 mw10 = (u32)m1, mw11 = (u32)(m1 >> 32);
        __syncthreads();

        const float L0 = si[lr], L1 = si[lr + 8];
        float sacc[8][4];
        #pragma unroll
        for (int j = 0; j < 8; ++j) {
            sacc[j][0] = L0; sacc[j][1] = L0;
            sacc[j][2] = L1; sacc[j][3] = L1;
        }
        #pragma unroll
        for (int s = 0; s < 4; ++s) {
            u32 qh[4], ql[4], kh[4][4], kl[4][4];
            u32 qa = sb + QH_OFF + (wm * 16 + qlr) * STB + (s * 16 + qlc) * 2;
            LDSM4(qa, qh[0], qh[1], qh[2], qh[3]);
            LDSM4(qa + (QL_OFF - QH_OFF), ql[0], ql[1], ql[2], ql[3]);
            #pragma unroll
            for (int g = 0; g < 4; ++g) {
                u32 ka = sb + KH_OFF + (wn * 64 + g * 16 + klr) * STB + (s * 16 + klc) * 2;
                LDSM4(ka, kh[g][0], kh[g][1], kh[g][2], kh[g][3]);
                LDSM4(ka + (KL_OFF - KH_OFF), kl[g][0], kl[g][1], kl[g][2], kl[g][3]);
            }
            #pragma unroll
            for (int j = 0; j < 8; ++j) {
                int g = j >> 1, se = (j & 1) << 1;
                MMA(sacc[j], qh[0], qh[1], qh[2], qh[3], kh[g][se], kh[g][se + 1]);
                MMA(sacc[j], ql[0], ql[1], ql[2], ql[3], kh[g][se], kh[g][se + 1]);
                MMA(sacc[j], qh[0], qh[1], qh[2], qh[3], kl[g][se], kl[g][se + 1]);
            }
        }

        // epilogue: p = 2^(s + rowlg) (normalized); mask; STG; split -> P frags
        u32 psh[4][4], psl[4][4];
        #pragma unroll
        for (int j = 0; j < 8; ++j) {
            int bit = (j * 8 + (lane & 3) * 2) & 31;
            u32 w0 = (j < 4) ? mw00 : mw01, w1 = (j < 4) ? mw10 : mw11;
            float e0 = ((w0 >> bit) & 1u) ? fexp2_4(sacc[j][0]) : 0.f;
            float e1 = ((w0 >> (bit + 1)) & 1u) ? fexp2_4(sacc[j][1]) : 0.f;
            float e2 = ((w1 >> bit) & 1u) ? fexp2_4(sacc[j][2]) : 0.f;
            float e3 = ((w1 >> (bit + 1)) & 1u) ? fexp2_4(sacc[j][3]) : 0.f;
            long col = (long)kt * 128 + wn * 64 + j * 8 + (lane & 3) * 2;
            *(float2*)(ab + (long)lr * 2048 + col)       = make_float2(e0, e1);
            *(float2*)(ab + (long)(lr + 8) * 2048 + col) = make_float2(e2, e3);
            sacc[j][0] = e0; sacc[j][1] = e1; sacc[j][2] = e2; sacc[j][3] = e3;
        }
        #pragma unroll
        for (int jj = 0; jj < 4; ++jj) {
            split2(sacc[2 * jj][0],     sacc[2 * jj][1],     psh[jj][0], psl[jj][0]);
            split2(sacc[2 * jj][2],     sacc[2 * jj][3],     psh[jj][1], psl[jj][1]);
            split2(sacc[2 * jj + 1][0], sacc[2 * jj + 1][1], psh[jj][2], psl[jj][2]);
            split2(sacc[2 * jj + 1][2], sacc[2 * jj + 1][3], psh[jj][3], psl[jj][3]);
        }

        #pragma unroll
        for (int jj = 0; jj < 4; ++jj) {
            u32 vh[4][4], vl[4][4];
            #pragma unroll
            for (int g = 0; g < 4; ++g) {
                u32 va = sb + VH_OFF + (wn * 64 + jj * 16 + vlr) * STB + (g * 16 + vlc) * 2;
                LDSM4T(va, vh[g][0], vh[g][1], vh[g][2], vh[g][3]);
                LDSM4T(va + (VL_OFF - VH_OFF), vl[g][0], vl[g][1], vl[g][2], vl[g][3]);
            }
            #pragma unroll
            for (int dn = 0; dn < 8; ++dn) {
                int g = dn >> 1, se = (dn & 1) << 1;
                MMA(oacc[dn], psh[jj][0], psh[jj][1], psh[jj][2], psh[jj][3], vh[g][se], vh[g][se + 1]);
                MMA(oacc[dn], psl[jj][0], psl[jj][1], psl[jj][2], psl[jj][3], vh[g][se], vh[g][se + 1]);
                MMA(oacc[dn], psh[jj][0], psh[jj][1], psh[jj][2], psh[jj][3], vl[g][se], vl[g][se + 1]);
            }
        }
    }

    __syncthreads();
    float* osm = (float*)smem;
    if (wn == 1) {
        #pragma unroll
        for (int dn = 0; dn < 8; ++dn) {
            int c = dn * 8 + (lane & 3) * 2;
            *(float2*)&osm[lr * 66 + c]       = make_float2(oacc[dn][0], oacc[dn][1]);
            *(float2*)&osm[(lr + 8) * 66 + c] = make_float2(oacc[dn][2], oacc[dn][3]);
        }
    }
    __syncthreads();
    if (wn == 0) {
        #pragma unroll
        for (int dn = 0; dn < 8; ++dn) {
            int c = dn * 8 + (lane & 3) * 2;
            float2 p0 = *(float2*)&osm[lr * 66 + c];
            float2 p1 = *(float2*)&osm[(lr + 8) * 66 + c];
            *(float2*)(ob + (long)lr * 64 + c) =
                make_float2(oacc[dn][0] + p0.x, oacc[dn][1] + p0.y);
            *(float2*)(ob + (long)(lr + 8) * 64 + c) =
                make_float2(oacc[dn][2] + p1.x, oacc[dn][3] + p1.y);
        }
    }
}

extern "C" void kernel_launch(void* const* d_in, const int* in_sizes, int n_in,
                              void* d_out, int out_size) {
    const float* q = (const float*)d_in[0];
    const float* k = (const float*)d_in[1];
    const float* v = (const float*)d_in[2];
    const int* mask = (const int*)d_in[3];
    float* out = (float*)d_out;
    float* attn = out + (long)2 * 16 * 2048 * 64;

    cudaFuncSetAttribute(rowsum, cudaFuncAttributeMaxDynamicSharedMemorySize, RS_TOTAL);
    cudaFuncSetAttribute(attn_hmma, cudaFuncAttributeMaxDynamicSharedMemorySize, SM_TOTAL);
    pack_mask<<<(2L * 2048 * 2048 / 4) / 256, 256>>>((const int4*)mask);
    rowsum<<<dim3(32, 16, 2), 256, RS_TOTAL>>>(q, k);
    attn_hmma<<<dim3(32, 16, 2), 256, SM_TOTAL>>>(q, k, v, out, attn);
}